// round 5
// baseline (speedup 1.0000x reference)
#include <cuda_runtime.h>
#include <cstdint>
#include <math.h>

#define NQ     16
#define DIM    65536
#define BATCH  64
#define NCLS   23
#define CHUNK  4096
#define NCHUNK 16
#define TPB    256

typedef unsigned long long ull;
typedef unsigned int u32;

// 32 MB statevector scratch + measurement partials
__device__ ull   g_state[BATCH * DIM];
__device__ float g_part[BATCH][NCHUNK][NQ];

// ---------------- packed f32x2 helpers ----------------
__device__ __forceinline__ ull pk(float x, float y) {
    ull r; asm("mov.b64 %0,{%1,%2};" : "=l"(r) : "f"(x), "f"(y)); return r;
}
__device__ __forceinline__ ull bc(float x) { return pk(x, x); }
__device__ __forceinline__ void upk(ull a, float& x, float& y) {
    asm("mov.b64 {%0,%1},%2;" : "=f"(x), "=f"(y) : "l"(a));
}
__device__ __forceinline__ ull f2mul(ull a, ull b) {
    ull r; asm("mul.rn.f32x2 %0,%1,%2;" : "=l"(r) : "l"(a), "l"(b)); return r;
}
__device__ __forceinline__ ull f2fma(ull a, ull b, ull c) {
    ull r; asm("fma.rn.f32x2 %0,%1,%2,%3;" : "=l"(r) : "l"(a), "l"(b), "l"(c)); return r;
}
// (re,im) -> (im,re); sign handling folded into broadcast constants
__device__ __forceinline__ ull swp(ull a) {
    float x, y; upk(a, x, y); return pk(y, x);
}

// ---------------- cluster / DSMEM helpers ----------------
__device__ __forceinline__ u32 smem_u32(const void* p) {
    u32 a;
    asm("{ .reg .u64 t; cvta.to.shared.u64 t, %1; cvt.u32.u64 %0, t; }" : "=r"(a) : "l"(p));
    return a;
}
__device__ __forceinline__ u32 mapa_u32(u32 addr, u32 rank) {
    u32 r; asm("mapa.shared::cluster.u32 %0, %1, %2;" : "=r"(r) : "r"(addr), "r"(rank));
    return r;
}
__device__ __forceinline__ ull ld_dsmem64(u32 addr) {
    ull v; asm volatile("ld.shared::cluster.b64 %0, [%1];" : "=l"(v) : "r"(addr)); return v;
}
#define CLUSTER_SYNC() do { \
    asm volatile("barrier.cluster.arrive.aligned;" ::: "memory"); \
    asm volatile("barrier.cluster.wait.aligned;"   ::: "memory"); } while (0)

// ---------------- register gates (16 amps / thread = 4 hypercube bits) -----
// fused 2x2 U on register bit RB; u = {u0x, v0y, u1x, v1y, u2x, v2y, u3x, v3y}
template<int RB>
__device__ __forceinline__ void gU(ull* a, const ull* __restrict__ u) {
    ull u0x = u[0], v0y = u[1], u1x = u[2], v1y = u[3];
    ull u2x = u[4], v2y = u[5], u3x = u[6], v3y = u[7];
#pragma unroll
    for (int m = 0; m < 8; m++) {
        int i0 = ((m >> RB) << (RB + 1)) | (m & ((1 << RB) - 1));
        int i1 = i0 | (1 << RB);
        ull a0 = a[i0], a1 = a[i1];
        ull s0 = swp(a0), s1 = swp(a1);
        a[i0] = f2fma(s1, v1y, f2fma(a1, u1x, f2fma(s0, v0y, f2mul(a0, u0x))));
        a[i1] = f2fma(s1, v3y, f2fma(a1, u3x, f2fma(s0, v2y, f2mul(a0, u2x))));
    }
}
// RX on register bit RB: cp = bc(cos), vs = pk(sin, -sin)
template<int RB>
__device__ __forceinline__ void gRX(ull* a, ull cp, ull vs) {
#pragma unroll
    for (int m = 0; m < 8; m++) {
        int i0 = ((m >> RB) << (RB + 1)) | (m & ((1 << RB) - 1));
        int i1 = i0 | (1 << RB);
        ull a0 = a[i0], a1 = a[i1];
        a[i0] = f2fma(swp(a1), vs, f2mul(a0, cp));
        a[i1] = f2fma(swp(a0), vs, f2mul(a1, cp));
    }
}
// CRX: ctrl = register bit CB, target = register bit RB
template<int RB, int CB>
__device__ __forceinline__ void gCRX(ull* a, ull cp, ull vs) {
#pragma unroll
    for (int m = 0; m < 8; m++) {
        int i0 = ((m >> RB) << (RB + 1)) | (m & ((1 << RB) - 1));
        if (!((i0 >> CB) & 1)) continue;
        int i1 = i0 | (1 << RB);
        ull a0 = a[i0], a1 = a[i1];
        a[i0] = f2fma(swp(a1), vs, f2mul(a0, cp));
        a[i1] = f2fma(swp(a0), vs, f2mul(a1, cp));
    }
}

// ---------------- layouts & transposes ----------------
// layout 0 (H): reg bits = local 8-11 :  i = r*256 + t
// layout 1 (L): reg bits = local 0-3  :  i = t*16 + r
// layout 2 (M): reg bits = local 4-7  :  i = (t>>4)*256 + r*16 + (t&15)
template<int L>
__device__ __forceinline__ int lidx(int r, int t) {
    return L == 0 ? ((r << 8) | t)
         : L == 1 ? ((t << 4) | r)
                  : (((t >> 4) << 8) | (r << 4) | (t & 15));
}
__device__ __forceinline__ int swz(int i) { return i ^ ((i >> 4) & 0xF); }

template<int F, int T>
__device__ __forceinline__ void xpose(ull* a, ull* s, int t) {
    __syncthreads();
#pragma unroll
    for (int r = 0; r < 16; r++) s[swz(lidx<F>(r, t))] = a[r];
    __syncthreads();
#pragma unroll
    for (int r = 0; r < 16; r++) a[r] = s[swz(lidx<T>(r, t))];
}

// local -> global index maps
__device__ __forceinline__ int gA(int i, int cid) { return i | (cid << 12); }
__device__ __forceinline__ int gB(int i, int cid) { return (i & 0xFF) | (cid << 8) | ((i >> 8) << 12); }

// ---------------- shared gate-constant prep ----------------
__device__ __forceinline__ void prep_gates(
    int t, int b, int uLayer,
    const float* __restrict__ x,  const float* __restrict__ w0,
    const float* __restrict__ x0, const float* __restrict__ w1,
    const float* __restrict__ x1,
    ull (*sUU)[8], ull (*sCC0)[2], ull (*sCC1)[2])
{
    if (t < NQ) {
        const int bit = t;
        const int q   = 15 - bit;                     // wire (wire 0 = MSB)
        const float* w = (uLayer ? w1 : w0) + q * 3;
        float xq = x[b * NQ + q];
        float sx, cx; sincosf(0.5f * xq, &sx, &cx);
        float phi = w[0], th = w[1], om = w[2];
        float sth, cth; sincosf(0.5f * th, &sth, &cth);
        float sp, cp;   sincosf(0.5f * (phi + om), &sp, &cp);
        float sm, cm;   sincosf(0.5f * (phi - om), &sm, &cm);
        float2 ra = make_float2( cp * cth, -sp * cth);
        float2 rb = make_float2(-cm * sth, -sm * sth);
        float2 rc = make_float2( cm * sth, -sm * sth);
        float2 rd = make_float2( cp * cth,  sp * cth);
        float2 U0 = make_float2(ra.x * cx + rb.y * sx,  ra.y * cx - rb.x * sx);
        float2 U1 = make_float2(ra.y * sx + rb.x * cx, -ra.x * sx + rb.y * cx);
        float2 U2 = make_float2(rc.x * cx + rd.y * sx,  rc.y * cx - rd.x * sx);
        float2 U3 = make_float2(rc.y * sx + rd.x * cx, -rc.x * sx + rd.y * cx);
        sUU[bit][0] = bc(U0.x); sUU[bit][1] = pk(-U0.y, U0.y);
        sUU[bit][2] = bc(U1.x); sUU[bit][3] = pk(-U1.y, U1.y);
        sUU[bit][4] = bc(U2.x); sUU[bit][5] = pk(-U2.y, U2.y);
        sUU[bit][6] = bc(U3.x); sUU[bit][7] = pk(-U3.y, U3.y);
        float a0s, a0c; sincosf(0.5f * x0[q], &a0s, &a0c);
        sCC0[bit][0] = bc(a0c); sCC0[bit][1] = pk(a0s, -a0s);
        float a1s, a1c; sincosf(0.5f * x1[q], &a1s, &a1c);
        sCC1[bit][0] = bc(a1c); sCC1[bit][1] = pk(a1s, -a1s);
    }
    __syncthreads();
}

#define SMEM_DECL \
    __shared__ ull s[CHUNK]; \
    __shared__ ull sUU[NQ][8]; \
    __shared__ ull sCC0[NQ][2]; \
    __shared__ ull sCC1[NQ][2];

// ---------------------------------------------------------------------------
// Pass 1 (B map): init, U0{12-15}, CRX L0 (15,14)(14,13)(13,12), U0{0-3},{4-7}
__global__ __launch_bounds__(TPB, 4) void k_pass1(
    const float* __restrict__ x,  const float* __restrict__ w0,
    const float* __restrict__ x0, const float* __restrict__ w1,
    const float* __restrict__ x1)
{
    SMEM_DECL
    const int t = threadIdx.x, cid = blockIdx.x, b = blockIdx.y;
    prep_gates(t, b, 0, x, w0, x0, w1, x1, sUU, sCC0, sCC1);

    ull a[16];
    ull* gs = g_state + (size_t)b * DIM;
#pragma unroll
    for (int r = 0; r < 16; r++) a[r] = 0ull;
    if (t == 0 && cid == 0) a[0] = pk(1.0f, 0.0f);
    gU<0>(a, sUU[12]); gU<1>(a, sUU[13]); gU<2>(a, sUU[14]); gU<3>(a, sUU[15]);
    gCRX<2, 3>(a, sCC0[15][0], sCC0[15][1]);
    gCRX<1, 2>(a, sCC0[14][0], sCC0[14][1]);
    gCRX<0, 1>(a, sCC0[13][0], sCC0[13][1]);
    xpose<0, 1>(a, s, t);
    gU<0>(a, sUU[0]); gU<1>(a, sUU[1]); gU<2>(a, sUU[2]); gU<3>(a, sUU[3]);
    xpose<1, 2>(a, s, t);
    gU<0>(a, sUU[4]); gU<1>(a, sUU[5]); gU<2>(a, sUU[6]); gU<3>(a, sUU[7]);
#pragma unroll
    for (int r = 0; r < 16; r++) gs[gB(lidx<2>(r, t), cid)] = a[r];
}

// Pass 2 (A map): U0{8-11}, CRX L0 chain (12,11)...(1,0)
__global__ __launch_bounds__(TPB, 4) void k_pass2(
    const float* __restrict__ x,  const float* __restrict__ w0,
    const float* __restrict__ x0, const float* __restrict__ w1,
    const float* __restrict__ x1)
{
    SMEM_DECL
    const int t = threadIdx.x, cid = blockIdx.x, b = blockIdx.y;
    prep_gates(t, b, 0, x, w0, x0, w1, x1, sUU, sCC0, sCC1);

    ull a[16];
    ull* gs = g_state + (size_t)b * DIM;
#pragma unroll
    for (int r = 0; r < 16; r++) a[r] = gs[gA(lidx<0>(r, t), cid)];
    gU<0>(a, sUU[8]); gU<1>(a, sUU[9]); gU<2>(a, sUU[10]); gU<3>(a, sUU[11]);
    if (cid & 1) gRX<3>(a, sCC0[12][0], sCC0[12][1]);
    gCRX<2, 3>(a, sCC0[11][0], sCC0[11][1]);
    gCRX<1, 2>(a, sCC0[10][0], sCC0[10][1]);
    gCRX<0, 1>(a, sCC0[ 9][0], sCC0[ 9][1]);
    xpose<0, 2>(a, s, t);
    if ((t >> 4) & 1) gRX<3>(a, sCC0[8][0], sCC0[8][1]);
    gCRX<2, 3>(a, sCC0[7][0], sCC0[7][1]);
    gCRX<1, 2>(a, sCC0[6][0], sCC0[6][1]);
    gCRX<0, 1>(a, sCC0[5][0], sCC0[5][1]);
    xpose<2, 1>(a, s, t);
    if (t & 1) gRX<3>(a, sCC0[4][0], sCC0[4][1]);
    gCRX<2, 3>(a, sCC0[3][0], sCC0[3][1]);
    gCRX<1, 2>(a, sCC0[2][0], sCC0[2][1]);
    gCRX<0, 1>(a, sCC0[1][0], sCC0[1][1]);
    xpose<1, 2>(a, s, t);
#pragma unroll
    for (int r = 0; r < 16; r++) gs[gA(lidx<2>(r, t), cid)] = a[r];
}

// Pass 3 (B map): CRX L0 (0,15), U1{12-15}, CRX L1 (15,14)(14,13)(13,12), U1{0-3},{4-7}
__global__ __launch_bounds__(TPB, 4) void k_pass3(
    const float* __restrict__ x,  const float* __restrict__ w0,
    const float* __restrict__ x0, const float* __restrict__ w1,
    const float* __restrict__ x1)
{
    SMEM_DECL
    const int t = threadIdx.x, cid = blockIdx.x, b = blockIdx.y;
    prep_gates(t, b, 1, x, w0, x0, w1, x1, sUU, sCC0, sCC1);

    ull a[16];
    ull* gs = g_state + (size_t)b * DIM;
#pragma unroll
    for (int r = 0; r < 16; r++) a[r] = gs[gB(lidx<0>(r, t), cid)];
    if (t & 1) gRX<3>(a, sCC0[0][0], sCC0[0][1]);        // layer-0 CRX(0,15)
    gU<0>(a, sUU[12]); gU<1>(a, sUU[13]); gU<2>(a, sUU[14]); gU<3>(a, sUU[15]);
    gCRX<2, 3>(a, sCC1[15][0], sCC1[15][1]);
    gCRX<1, 2>(a, sCC1[14][0], sCC1[14][1]);
    gCRX<0, 1>(a, sCC1[13][0], sCC1[13][1]);
    xpose<0, 1>(a, s, t);
    gU<0>(a, sUU[0]); gU<1>(a, sUU[1]); gU<2>(a, sUU[2]); gU<3>(a, sUU[3]);
    xpose<1, 2>(a, s, t);
    gU<0>(a, sUU[4]); gU<1>(a, sUU[5]); gU<2>(a, sUU[6]); gU<3>(a, sUU[7]);
#pragma unroll
    for (int r = 0; r < 16; r++) gs[gB(lidx<2>(r, t), cid)] = a[r];
}

// Pass 4 (A map, 2-CTA cluster): U1{8-11}, CRX L1 chain, CRX(0,15) via DSMEM, measure.
// Cluster pairs blockIdx.x = {2k, 2k+1}; cid bit3 (= global bit 15) = rank.
__global__ __launch_bounds__(TPB) __cluster_dims__(2, 1, 1) void k_pass4(
    const float* __restrict__ x,  const float* __restrict__ w0,
    const float* __restrict__ x0, const float* __restrict__ w1,
    const float* __restrict__ x1)
{
    SMEM_DECL
    __shared__ float sred[8][NQ];
    const int t = threadIdx.x, b = blockIdx.y;
    const u32 rank = (u32)(blockIdx.x & 1);
    const int cid = (int)(((blockIdx.x >> 1) & 7) | ((blockIdx.x & 1) << 3));
    prep_gates(t, b, 1, x, w0, x0, w1, x1, sUU, sCC0, sCC1);

    ull a[16];
    ull* gs = g_state + (size_t)b * DIM;
#pragma unroll
    for (int r = 0; r < 16; r++) a[r] = gs[gA(lidx<0>(r, t), cid)];
    gU<0>(a, sUU[8]); gU<1>(a, sUU[9]); gU<2>(a, sUU[10]); gU<3>(a, sUU[11]);
    if (cid & 1) gRX<3>(a, sCC1[12][0], sCC1[12][1]);
    gCRX<2, 3>(a, sCC1[11][0], sCC1[11][1]);
    gCRX<1, 2>(a, sCC1[10][0], sCC1[10][1]);
    gCRX<0, 1>(a, sCC1[ 9][0], sCC1[ 9][1]);
    xpose<0, 2>(a, s, t);
    if ((t >> 4) & 1) gRX<3>(a, sCC1[8][0], sCC1[8][1]);
    gCRX<2, 3>(a, sCC1[7][0], sCC1[7][1]);
    gCRX<1, 2>(a, sCC1[6][0], sCC1[6][1]);
    gCRX<0, 1>(a, sCC1[5][0], sCC1[5][1]);
    xpose<2, 1>(a, s, t);
    if (t & 1) gRX<3>(a, sCC1[4][0], sCC1[4][1]);
    gCRX<2, 3>(a, sCC1[3][0], sCC1[3][1]);
    gCRX<1, 2>(a, sCC1[2][0], sCC1[2][1]);
    gCRX<0, 1>(a, sCC1[1][0], sCC1[1][1]);

    // ---- CRX(ctrl=global bit 0, tgt=global bit 15) across the cluster pair ----
    // L layout: local bit0 = r bit0 (ctrl); global bit15 = cid bit3 = rank (target).
    // Symmetric pair update: a_new = cos*a - i*sin*a_peer  (only for odd r).
    __syncthreads();
#pragma unroll
    for (int r = 0; r < 16; r++) s[swz(lidx<1>(r, t))] = a[r];
    __syncthreads();
    CLUSTER_SYNC();
    {
        ull cp = sCC1[0][0], vs = sCC1[0][1];
        u32 pbase = mapa_u32(smem_u32(s), rank ^ 1);
#pragma unroll
        for (int r = 1; r < 16; r += 2) {
            ull pa = ld_dsmem64(pbase + (u32)swz(lidx<1>(r, t)) * 8u);
            a[r] = f2fma(swp(pa), vs, f2mul(a[r], cp));
        }
    }
    CLUSTER_SYNC();   // peers done reading our smem

    // ---- measurement (L layout): bits 0-3 = r, 4-11 = t, 12-15 = cid ----
    float p[16], S = 0.0f;
#pragma unroll
    for (int r = 0; r < 16; r++) {
        float xx, yy; upk(a[r], xx, yy);
        p[r] = xx * xx + yy * yy;
        S += p[r];
    }
    float acc[NQ];
#pragma unroll
    for (int bit = 0; bit < 4; bit++) {
        float v = 0.0f;
#pragma unroll
        for (int r = 0; r < 16; r++) v += ((r >> bit) & 1) ? -p[r] : p[r];
        acc[bit] = v;
    }
#pragma unroll
    for (int bit = 4; bit < 12; bit++)  acc[bit] = ((t >> (bit - 4)) & 1) ? -S : S;
#pragma unroll
    for (int bit = 12; bit < 16; bit++) acc[bit] = ((cid >> (bit - 12)) & 1) ? -S : S;
#pragma unroll
    for (int i = 0; i < NQ; i++) {
#pragma unroll
        for (int o = 16; o >= 1; o >>= 1)
            acc[i] += __shfl_down_sync(0xFFFFFFFFu, acc[i], o);
    }
    __syncthreads();
    int warp = t >> 5, lane = t & 31;
    if (lane == 0) {
#pragma unroll
        for (int i = 0; i < NQ; i++) sred[warp][i] = acc[i];
    }
    __syncthreads();
    if (t < NQ) {
        float sum = 0.0f;
#pragma unroll
        for (int wI = 0; wI < 8; wI++) sum += sred[wI][t];
        g_part[b][cid][t] = sum;      // indexed by BIT
    }
}

// ---------------------------------------------------------------------------
__global__ void k_final(const float* __restrict__ fc_w,
                        const float* __restrict__ fc_b,
                        float* __restrict__ out) {
    int b = blockIdx.x;
    int t = threadIdx.x;
    __shared__ float feats[NQ];
    __shared__ float logits[NCLS];
    if (t < NQ) {
        float sum = 0.0f;
        int bit = 15 - t;                 // wire t measures bit (15 - t)
#pragma unroll
        for (int c = 0; c < NCHUNK; c++) sum += g_part[b][c][bit];
        feats[t] = sum;
    }
    __syncthreads();
    if (t < NCLS) {
        float z = fc_b[t];
#pragma unroll
        for (int wI = 0; wI < NQ; wI++) z += feats[wI] * fc_w[t * NQ + wI];
        logits[t] = z;
    }
    __syncthreads();
    if (t == 0) {
        float mx = logits[0];
        for (int c = 1; c < NCLS; c++) mx = fmaxf(mx, logits[c]);
        float sum = 0.0f;
        for (int c = 0; c < NCLS; c++) sum += expf(logits[c] - mx);
        float l = logf(sum) + mx;
        for (int c = 0; c < NCLS; c++) out[b * NCLS + c] = logits[c] - l;
    }
}

// ---------------------------------------------------------------------------
extern "C" void kernel_launch(void* const* d_in, const int* in_sizes, int n_in,
                              void* d_out, int out_size) {
    const float* x    = (const float*)d_in[0];
    const float* w0   = (const float*)d_in[1];
    const float* x0   = (const float*)d_in[2];
    const float* w1   = (const float*)d_in[3];
    const float* x1   = (const float*)d_in[4];
    const float* fc_w = (const float*)d_in[5];
    const float* fc_b = (const float*)d_in[6];
    float* out = (float*)d_out;

    dim3 grid(NCHUNK, BATCH);
    k_pass1<<<grid, TPB>>>(x, w0, x0, w1, x1);
    k_pass2<<<grid, TPB>>>(x, w0, x0, w1, x1);
    k_pass3<<<grid, TPB>>>(x, w0, x0, w1, x1);
    k_pass4<<<grid, TPB>>>(x, w0, x0, w1, x1);
    k_final<<<BATCH, 32>>>(fc_w, fc_b, out);
}

// round 7
// speedup vs baseline: 1.6808x; 1.6808x over previous
#include <cuda_runtime.h>
#include <cstdint>
#include <math.h>

#define NQ     16
#define DIM    65536
#define BATCH  64
#define NCLS   23
#define CHUNK  4096
#define NCHUNK 16
#define TPB    256

typedef unsigned long long ull;
typedef unsigned int u32;

// wire q -> physical bit
__constant__ int c_w2b[NQ] = {15,1,2,3,0,8,9,10,11,5,6,7,4,12,13,14};

// 32 MB statevector scratch + measurement partials
__device__ ull   g_state[BATCH * DIM];
__device__ float g_part[BATCH][NCHUNK][NQ];

// ---------------- packed f32x2 helpers ----------------
__device__ __forceinline__ ull pk(float x, float y) {
    ull r; asm("mov.b64 %0,{%1,%2};" : "=l"(r) : "f"(x), "f"(y)); return r;
}
__device__ __forceinline__ ull bc(float x) { return pk(x, x); }
__device__ __forceinline__ void upk(ull a, float& x, float& y) {
    asm("mov.b64 {%0,%1},%2;" : "=f"(x), "=f"(y) : "l"(a));
}
__device__ __forceinline__ ull f2mul(ull a, ull b) {
    ull r; asm("mul.rn.f32x2 %0,%1,%2;" : "=l"(r) : "l"(a), "l"(b)); return r;
}
__device__ __forceinline__ ull f2fma(ull a, ull b, ull c) {
    ull r; asm("fma.rn.f32x2 %0,%1,%2,%3;" : "=l"(r) : "l"(a), "l"(b), "l"(c)); return r;
}
// (re,im) -> (im,re); signs folded into broadcast constants
__device__ __forceinline__ ull swp(ull a) {
    float x, y; upk(a, x, y); return pk(y, x);
}
__device__ __forceinline__ float2 cmul(float2 a, float2 b) {
    return make_float2(a.x * b.x - a.y * b.y, a.x * b.y + a.y * b.x);
}

// ---------------- register gates (16 amps/thread = 4 hypercube bits) ------
// fused 2x2 U on register bit RB; u = {u0x, v0y, u1x, v1y, u2x, v2y, u3x, v3y}
template<int RB>
__device__ __forceinline__ void gU(ull* a, const ull* __restrict__ u) {
    ull u0x = u[0], v0y = u[1], u1x = u[2], v1y = u[3];
    ull u2x = u[4], v2y = u[5], u3x = u[6], v3y = u[7];
#pragma unroll
    for (int m = 0; m < 8; m++) {
        int i0 = ((m >> RB) << (RB + 1)) | (m & ((1 << RB) - 1));
        int i1 = i0 | (1 << RB);
        ull a0 = a[i0], a1 = a[i1];
        ull s0 = swp(a0), s1 = swp(a1);
        a[i0] = f2fma(s1, v1y, f2fma(a1, u1x, f2fma(s0, v0y, f2mul(a0, u0x))));
        a[i1] = f2fma(s1, v3y, f2fma(a1, u3x, f2fma(s0, v2y, f2mul(a0, u2x))));
    }
}
// RX on register bit RB: cp = bc(cos), vs = pk(sin, -sin)
template<int RB>
__device__ __forceinline__ void gRX(ull* a, ull cp, ull vs) {
#pragma unroll
    for (int m = 0; m < 8; m++) {
        int i0 = ((m >> RB) << (RB + 1)) | (m & ((1 << RB) - 1));
        int i1 = i0 | (1 << RB);
        ull a0 = a[i0], a1 = a[i1];
        a[i0] = f2fma(swp(a1), vs, f2mul(a0, cp));
        a[i1] = f2fma(swp(a0), vs, f2mul(a1, cp));
    }
}
// CRX: ctrl = register bit CB, target = register bit RB
template<int RB, int CB>
__device__ __forceinline__ void gCRX(ull* a, ull cp, ull vs) {
#pragma unroll
    for (int m = 0; m < 8; m++) {
        int i0 = ((m >> RB) << (RB + 1)) | (m & ((1 << RB) - 1));
        if (!((i0 >> CB) & 1)) continue;
        int i1 = i0 | (1 << RB);
        ull a0 = a[i0], a1 = a[i1];
        a[i0] = f2fma(swp(a1), vs, f2mul(a0, cp));
        a[i1] = f2fma(swp(a0), vs, f2mul(a1, cp));
    }
}

// ---------------- layouts & transposes ----------------
// layout 0 (H): reg = local bits 8-11 :  i = r*256 + t
// layout 1 (L): reg = local bits 0-3  :  i = t*16 + r
// layout 2 (M): reg = local bits 4-7  :  i = (t>>4)*256 + r*16 + (t&15)
template<int L>
__device__ __forceinline__ int lidx(int r, int t) {
    return L == 0 ? ((r << 8) | t)
         : L == 1 ? ((t << 4) | r)
                  : (((t >> 4) << 8) | (r << 4) | (t & 15));
}
__device__ __forceinline__ int swz(int i) { return i ^ ((i >> 4) & 0xF); }

template<int F, int T>
__device__ __forceinline__ void xpose(ull* a, ull* s, int t) {
    __syncthreads();
#pragma unroll
    for (int r = 0; r < 16; r++) s[swz(lidx<F>(r, t))] = a[r];
    __syncthreads();
#pragma unroll
    for (int r = 0; r < 16; r++) a[r] = s[swz(lidx<T>(r, t))];
}

// local -> global maps. A: chunk = bits 12-15. B: chunk = bits 8-11.
__device__ __forceinline__ int gA(int i, int cid) { return i | (cid << 12); }
__device__ __forceinline__ int gB(int i, int cid) { return (i & 0xFF) | (cid << 8) | ((i >> 8) << 12); }

// ---------------- shared gate-constant prep (indexed by WIRE) ----------------
// sUU[q][8]: folded fused (Rot_layer ∘ RX) for wire q
// sF[bit][2]: raw column-0 of U0 for the wire assigned to that bit (for init)
// sCC0/sCC1[q][2]: folded CRX {bc(cos), pk(sin,-sin)} for ctrl wire q
__device__ __forceinline__ void prep_gates(
    int t, int b, int uLayer,
    const float* __restrict__ x,  const float* __restrict__ w0,
    const float* __restrict__ x0, const float* __restrict__ w1,
    const float* __restrict__ x1,
    ull (*sUU)[8], float2 (*sF)[2], ull (*sCC0)[2], ull (*sCC1)[2])
{
    if (t < NQ) {
        const int q = t;                              // wire
        const float* w = (uLayer ? w1 : w0) + q * 3;
        float xq = x[b * NQ + q];
        float sx, cx; sincosf(0.5f * xq, &sx, &cx);
        float phi = w[0], th = w[1], om = w[2];
        float sth, cth; sincosf(0.5f * th, &sth, &cth);
        float sp, cp;   sincosf(0.5f * (phi + om), &sp, &cp);
        float sm, cm;   sincosf(0.5f * (phi - om), &sm, &cm);
        float2 ra = make_float2( cp * cth, -sp * cth);
        float2 rb = make_float2(-cm * sth, -sm * sth);
        float2 rc = make_float2( cm * sth, -sm * sth);
        float2 rd = make_float2( cp * cth,  sp * cth);
        float2 U0 = make_float2(ra.x * cx + rb.y * sx,  ra.y * cx - rb.x * sx);
        float2 U1 = make_float2(ra.y * sx + rb.x * cx, -ra.x * sx + rb.y * cx);
        float2 U2 = make_float2(rc.x * cx + rd.y * sx,  rc.y * cx - rd.x * sx);
        float2 U3 = make_float2(rc.y * sx + rd.x * cx, -rc.x * sx + rd.y * cx);
        sUU[q][0] = bc(U0.x); sUU[q][1] = pk(-U0.y, U0.y);
        sUU[q][2] = bc(U1.x); sUU[q][3] = pk(-U1.y, U1.y);
        sUU[q][4] = bc(U2.x); sUU[q][5] = pk(-U2.y, U2.y);
        sUU[q][6] = bc(U3.x); sUU[q][7] = pk(-U3.y, U3.y);
        if (sF) {                                      // init factors (layer 0 only)
            int bit = c_w2b[q];
            sF[bit][0] = U0;                           // entry (0,0)
            sF[bit][1] = U2;                           // entry (1,0)
        }
        float a0s, a0c; sincosf(0.5f * x0[q], &a0s, &a0c);
        sCC0[q][0] = bc(a0c); sCC0[q][1] = pk(a0s, -a0s);
        float a1s, a1c; sincosf(0.5f * x1[q], &a1s, &a1c);
        sCC1[q][0] = bc(a1c); sCC1[q][1] = pk(a1s, -a1s);
    }
    __syncthreads();
}

#define SMEM_DECL \
    __shared__ ull s[CHUNK]; \
    __shared__ ull sUU[NQ][8]; \
    __shared__ ull sCC0[NQ][2]; \
    __shared__ ull sCC1[NQ][2];

// ---------------------------------------------------------------------------
// Pass 1 (map A, store only): product init (all U0), CRX_0..3 [L], CRX_4..7 [H]
__global__ __launch_bounds__(TPB) void k_pass1(
    const float* __restrict__ x,  const float* __restrict__ w0,
    const float* __restrict__ x0, const float* __restrict__ w1,
    const float* __restrict__ x1)
{
    SMEM_DECL
    __shared__ float2 sF[NQ][2];
    const int t = threadIdx.x, cid = blockIdx.x, b = blockIdx.y;
    prep_gates(t, b, 0, x, w0, x0, w1, x1, sUU, sF, sCC0, sCC1);

    ull a[16];
    ull* gs = g_state + (size_t)b * DIM;

    // ---- product init in L layout: g bits 0-3 = r, 4-11 = t, 12-15 = cid ----
    {
        float2 pref = make_float2(1.0f, 0.0f);
#pragma unroll
        for (int bbit = 4; bbit < 12; bbit++)
            pref = cmul(pref, sF[bbit][(t >> (bbit - 4)) & 1]);
#pragma unroll
        for (int bbit = 12; bbit < 16; bbit++)
            pref = cmul(pref, sF[bbit][(cid >> (bbit - 12)) & 1]);
        float2 g01[4], g23[4];
#pragma unroll
        for (int i = 0; i < 4; i++) {
            g01[i] = cmul(sF[0][i & 1], sF[1][(i >> 1) & 1]);
            g23[i] = cmul(sF[2][i & 1], sF[3][(i >> 1) & 1]);
        }
#pragma unroll
        for (int r = 0; r < 16; r++) {
            float2 v = cmul(pref, cmul(g01[r & 3], g23[r >> 2]));
            a[r] = pk(v.x, v.y);
        }
    }
    // L: reg bits = g bits 0-3
    if ((cid >> 3) & 1) gRX<1>(a, sCC0[0][0], sCC0[0][1]);   // CRX_0: ctrl w0(bit15=cid3), tgt w1(bit1)
    gCRX<2, 1>(a, sCC0[1][0], sCC0[1][1]);                    // CRX_1: bit1 -> bit2
    gCRX<3, 2>(a, sCC0[2][0], sCC0[2][1]);                    // CRX_2: bit2 -> bit3
    gCRX<0, 3>(a, sCC0[3][0], sCC0[3][1]);                    // CRX_3: bit3 -> bit0
    xpose<1, 0>(a, s, t);
    // H: reg bits = g bits 8-11; g bits 0-7 = t
    if (t & 1) gRX<0>(a, sCC0[4][0], sCC0[4][1]);             // CRX_4: ctrl w4(bit0), tgt w5(bit8)
    gCRX<1, 0>(a, sCC0[5][0], sCC0[5][1]);                    // CRX_5: bit8 -> bit9
    gCRX<2, 1>(a, sCC0[6][0], sCC0[6][1]);                    // CRX_6
    gCRX<3, 2>(a, sCC0[7][0], sCC0[7][1]);                    // CRX_7
#pragma unroll
    for (int r = 0; r < 16; r++) gs[gA(lidx<0>(r, t), cid)] = a[r];
}

// Pass 2 (map B): CRX_8..11 [M], CRX_12..15 + U1_w0 [H]
__global__ __launch_bounds__(TPB) void k_pass2(
    const float* __restrict__ x,  const float* __restrict__ w0,
    const float* __restrict__ x0, const float* __restrict__ w1,
    const float* __restrict__ x1)
{
    SMEM_DECL
    const int t = threadIdx.x, cid = blockIdx.x, b = blockIdx.y;
    prep_gates(t, b, 1, x, w0, x0, w1, x1, sUU, nullptr, sCC0, sCC1);

    ull a[16];
    ull* gs = g_state + (size_t)b * DIM;
    // M layout, map B: g bits 0-3 = t&15, 4-7 = r, 8-11 = cid, 12-15 = t>>4
#pragma unroll
    for (int r = 0; r < 16; r++) a[r] = gs[gB(lidx<2>(r, t), cid)];
    if ((cid >> 3) & 1) gRX<1>(a, sCC0[8][0], sCC0[8][1]);    // CRX_8: ctrl w8(bit11=cid3), tgt w9(bit5)
    gCRX<2, 1>(a, sCC0[ 9][0], sCC0[ 9][1]);                  // CRX_9: bit5 -> bit6
    gCRX<3, 2>(a, sCC0[10][0], sCC0[10][1]);                  // CRX_10
    gCRX<0, 3>(a, sCC0[11][0], sCC0[11][1]);                  // CRX_11: ctrl bit7, tgt w12(bit4)
    xpose<2, 0>(a, s, t);
    // H layout, map B: g bits 0-7 = t, 8-11 = cid, 12-15 = r
    if ((t >> 4) & 1) gRX<0>(a, sCC0[12][0], sCC0[12][1]);    // CRX_12: ctrl w12(bit4), tgt w13(bit12)
    gCRX<1, 0>(a, sCC0[13][0], sCC0[13][1]);                  // CRX_13: bit12 -> bit13
    gCRX<2, 1>(a, sCC0[14][0], sCC0[14][1]);                  // CRX_14
    gCRX<3, 2>(a, sCC0[15][0], sCC0[15][1]);                  // CRX_15: ctrl bit14, tgt w0(bit15)
    gU<3>(a, sUU[0]);                                          // U1 on w0 (bit15 = r3)
#pragma unroll
    for (int r = 0; r < 16; r++) gs[gB(lidx<0>(r, t), cid)] = a[r];
}

// Pass 3 (map A): U1{w12,w9,w10,w11} [M], U1{w1..w4}+CRX_0..3(L1) [L],
//                 U1{w5..w8}+CRX_4..7(L1) [H]
__global__ __launch_bounds__(TPB) void k_pass3(
    const float* __restrict__ x,  const float* __restrict__ w0,
    const float* __restrict__ x0, const float* __restrict__ w1,
    const float* __restrict__ x1)
{
    SMEM_DECL
    const int t = threadIdx.x, cid = blockIdx.x, b = blockIdx.y;
    prep_gates(t, b, 1, x, w0, x0, w1, x1, sUU, nullptr, sCC0, sCC1);

    ull a[16];
    ull* gs = g_state + (size_t)b * DIM;
    // M layout, map A: g bits 0-3 = t&15, 4-7 = r, 8-11 = t>>4, 12-15 = cid
#pragma unroll
    for (int r = 0; r < 16; r++) a[r] = gs[gA(lidx<2>(r, t), cid)];
    gU<0>(a, sUU[12]); gU<1>(a, sUU[9]); gU<2>(a, sUU[10]); gU<3>(a, sUU[11]);
    xpose<2, 1>(a, s, t);
    // L layout: g bits 0-3 = r, 4-11 = t, 12-15 = cid
    gU<1>(a, sUU[1]); gU<2>(a, sUU[2]); gU<3>(a, sUU[3]); gU<0>(a, sUU[4]);
    if ((cid >> 3) & 1) gRX<1>(a, sCC1[0][0], sCC1[0][1]);    // CRX_0 (L1)
    gCRX<2, 1>(a, sCC1[1][0], sCC1[1][1]);
    gCRX<3, 2>(a, sCC1[2][0], sCC1[2][1]);
    gCRX<0, 3>(a, sCC1[3][0], sCC1[3][1]);
    xpose<1, 0>(a, s, t);
    // H layout: g bits 0-7 = t, 8-11 = r, 12-15 = cid
    gU<0>(a, sUU[5]); gU<1>(a, sUU[6]); gU<2>(a, sUU[7]); gU<3>(a, sUU[8]);
    if (t & 1) gRX<0>(a, sCC1[4][0], sCC1[4][1]);             // CRX_4 (L1)
    gCRX<1, 0>(a, sCC1[5][0], sCC1[5][1]);
    gCRX<2, 1>(a, sCC1[6][0], sCC1[6][1]);
    gCRX<3, 2>(a, sCC1[7][0], sCC1[7][1]);
#pragma unroll
    for (int r = 0; r < 16; r++) gs[gA(lidx<0>(r, t), cid)] = a[r];
}

// Pass 4 (map B, load only): CRX_8..11(L1) [M], U1{w13,w14,w15}+CRX_12..15(L1) [H],
//                            measurement in registers.
__global__ __launch_bounds__(TPB) void k_pass4(
    const float* __restrict__ x,  const float* __restrict__ w0,
    const float* __restrict__ x0, const float* __restrict__ w1,
    const float* __restrict__ x1)
{
    SMEM_DECL
    __shared__ float sred[8][NQ];
    const int t = threadIdx.x, cid = blockIdx.x, b = blockIdx.y;
    prep_gates(t, b, 1, x, w0, x0, w1, x1, sUU, nullptr, sCC0, sCC1);

    ull a[16];
    ull* gs = g_state + (size_t)b * DIM;
#pragma unroll
    for (int r = 0; r < 16; r++) a[r] = gs[gB(lidx<2>(r, t), cid)];
    if ((cid >> 3) & 1) gRX<1>(a, sCC1[8][0], sCC1[8][1]);    // CRX_8 (L1)
    gCRX<2, 1>(a, sCC1[ 9][0], sCC1[ 9][1]);
    gCRX<3, 2>(a, sCC1[10][0], sCC1[10][1]);
    gCRX<0, 3>(a, sCC1[11][0], sCC1[11][1]);
    xpose<2, 0>(a, s, t);
    // H layout, map B: g bits 0-7 = t, 8-11 = cid, 12-15 = r
    gU<0>(a, sUU[13]); gU<1>(a, sUU[14]); gU<2>(a, sUU[15]);
    if ((t >> 4) & 1) gRX<0>(a, sCC1[12][0], sCC1[12][1]);    // CRX_12 (L1)
    gCRX<1, 0>(a, sCC1[13][0], sCC1[13][1]);
    gCRX<2, 1>(a, sCC1[14][0], sCC1[14][1]);
    gCRX<3, 2>(a, sCC1[15][0], sCC1[15][1]);                  // CRX_15 (L1)

    // ---- measurement: g bits 0-7 = t, 8-11 = cid, 12-15 = r ----
    float p[16], S = 0.0f;
#pragma unroll
    for (int r = 0; r < 16; r++) {
        float xx, yy; upk(a[r], xx, yy);
        p[r] = xx * xx + yy * yy;
        S += p[r];
    }
    float acc[NQ];
#pragma unroll
    for (int bit = 0; bit < 8; bit++)   acc[bit] = ((t >> bit) & 1) ? -S : S;
#pragma unroll
    for (int bit = 8; bit < 12; bit++)  acc[bit] = ((cid >> (bit - 8)) & 1) ? -S : S;
#pragma unroll
    for (int bit = 12; bit < 16; bit++) {
        float v = 0.0f;
#pragma unroll
        for (int r = 0; r < 16; r++) v += ((r >> (bit - 12)) & 1) ? -p[r] : p[r];
        acc[bit] = v;
    }
#pragma unroll
    for (int i = 0; i < NQ; i++) {
#pragma unroll
        for (int o = 16; o >= 1; o >>= 1)
            acc[i] += __shfl_down_sync(0xFFFFFFFFu, acc[i], o);
    }
    __syncthreads();
    int warp = t >> 5, lane = t & 31;
    if (lane == 0) {
#pragma unroll
        for (int i = 0; i < NQ; i++) sred[warp][i] = acc[i];
    }
    __syncthreads();
    if (t < NQ) {
        float sum = 0.0f;
#pragma unroll
        for (int wI = 0; wI < 8; wI++) sum += sred[wI][t];
        g_part[b][cid][t] = sum;      // indexed by BIT
    }
}

// ---------------------------------------------------------------------------
__global__ void k_final(const float* __restrict__ fc_w,
                        const float* __restrict__ fc_b,
                        float* __restrict__ out) {
    int b = blockIdx.x;
    int t = threadIdx.x;
    __shared__ float feats[NQ];
    __shared__ float logits[NCLS];
    if (t < NQ) {
        float sum = 0.0f;
        int bit = c_w2b[t];               // wire t measures its assigned bit
#pragma unroll
        for (int c = 0; c < NCHUNK; c++) sum += g_part[b][c][bit];
        feats[t] = sum;
    }
    __syncthreads();
    if (t < NCLS) {
        float z = fc_b[t];
#pragma unroll
        for (int wI = 0; wI < NQ; wI++) z += feats[wI] * fc_w[t * NQ + wI];
        logits[t] = z;
    }
    __syncthreads();
    if (t == 0) {
        float mx = logits[0];
        for (int c = 1; c < NCLS; c++) mx = fmaxf(mx, logits[c]);
        float sum = 0.0f;
        for (int c = 0; c < NCLS; c++) sum += expf(logits[c] - mx);
        float l = logf(sum) + mx;
        for (int c = 0; c < NCLS; c++) out[b * NCLS + c] = logits[c] - l;
    }
}

// ---------------------------------------------------------------------------
extern "C" void kernel_launch(void* const* d_in, const int* in_sizes, int n_in,
                              void* d_out, int out_size) {
    const float* x    = (const float*)d_in[0];
    const float* w0   = (const float*)d_in[1];
    const float* x0   = (const float*)d_in[2];
    const float* w1   = (const float*)d_in[3];
    const float* x1   = (const float*)d_in[4];
    const float* fc_w = (const float*)d_in[5];
    const float* fc_b = (const float*)d_in[6];
    float* out = (float*)d_out;

    dim3 grid(NCHUNK, BATCH);
    k_pass1<<<grid, TPB>>>(x, w0, x0, w1, x1);
    k_pass2<<<grid, TPB>>>(x, w0, x0, w1, x1);
    k_pass3<<<grid, TPB>>>(x, w0, x0, w1, x1);
    k_pass4<<<grid, TPB>>>(x, w0, x0, w1, x1);
    k_final<<<BATCH, 32>>>(fc_w, fc_b, out);
}

// round 8
// speedup vs baseline: 1.7949x; 1.0678x over previous
#include <cuda_runtime.h>
#include <cstdint>
#include <math.h>

#define NQ     16
#define DIM    65536
#define BATCH  64
#define NCLS   23
#define CHUNK  4096
#define NCHUNK 16
#define TPB    256

typedef unsigned long long ull;
typedef unsigned int u32;

// wire q -> physical bit:  w0->15, w1..w15 -> 0..14
__constant__ int c_w2b[NQ] = {15,0,1,2,3,4,5,6,7,8,9,10,11,12,13,14};

// 32 MB statevector scratch + measurement partials
__device__ ull   g_state[BATCH * DIM];
__device__ float g_part[BATCH][NCHUNK][NQ];

// ---------------- packed f32x2 helpers ----------------
__device__ __forceinline__ ull pk(float x, float y) {
    ull r; asm("mov.b64 %0,{%1,%2};" : "=l"(r) : "f"(x), "f"(y)); return r;
}
__device__ __forceinline__ ull bc(float x) { return pk(x, x); }
__device__ __forceinline__ void upk(ull a, float& x, float& y) {
    asm("mov.b64 {%0,%1},%2;" : "=f"(x), "=f"(y) : "l"(a));
}
__device__ __forceinline__ ull f2mul(ull a, ull b) {
    ull r; asm("mul.rn.f32x2 %0,%1,%2;" : "=l"(r) : "l"(a), "l"(b)); return r;
}
__device__ __forceinline__ ull f2fma(ull a, ull b, ull c) {
    ull r; asm("fma.rn.f32x2 %0,%1,%2,%3;" : "=l"(r) : "l"(a), "l"(b), "l"(c)); return r;
}
// (re,im) -> (im,re); signs folded into broadcast constants
__device__ __forceinline__ ull swp(ull a) {
    float x, y; upk(a, x, y); return pk(y, x);
}
__device__ __forceinline__ float2 cmul(float2 a, float2 b) {
    return make_float2(a.x * b.x - a.y * b.y, a.x * b.y + a.y * b.x);
}

// ---------------- register gates (16 amps/thread = 4 hypercube bits) ------
template<int RB>
__device__ __forceinline__ void gU(ull* a, const ull* __restrict__ u) {
    ull u0x = u[0], v0y = u[1], u1x = u[2], v1y = u[3];
    ull u2x = u[4], v2y = u[5], u3x = u[6], v3y = u[7];
#pragma unroll
    for (int m = 0; m < 8; m++) {
        int i0 = ((m >> RB) << (RB + 1)) | (m & ((1 << RB) - 1));
        int i1 = i0 | (1 << RB);
        ull a0 = a[i0], a1 = a[i1];
        ull s0 = swp(a0), s1 = swp(a1);
        a[i0] = f2fma(s1, v1y, f2fma(a1, u1x, f2fma(s0, v0y, f2mul(a0, u0x))));
        a[i1] = f2fma(s1, v3y, f2fma(a1, u3x, f2fma(s0, v2y, f2mul(a0, u2x))));
    }
}
// RX on register bit RB: cp = bc(cos), vs = pk(sin, -sin)
template<int RB>
__device__ __forceinline__ void gRX(ull* a, ull cp, ull vs) {
#pragma unroll
    for (int m = 0; m < 8; m++) {
        int i0 = ((m >> RB) << (RB + 1)) | (m & ((1 << RB) - 1));
        int i1 = i0 | (1 << RB);
        ull a0 = a[i0], a1 = a[i1];
        a[i0] = f2fma(swp(a1), vs, f2mul(a0, cp));
        a[i1] = f2fma(swp(a0), vs, f2mul(a1, cp));
    }
}
// CRX: ctrl = register bit CB, target = register bit RB
template<int RB, int CB>
__device__ __forceinline__ void gCRX(ull* a, ull cp, ull vs) {
#pragma unroll
    for (int m = 0; m < 8; m++) {
        int i0 = ((m >> RB) << (RB + 1)) | (m & ((1 << RB) - 1));
        if (!((i0 >> CB) & 1)) continue;
        int i1 = i0 | (1 << RB);
        ull a0 = a[i0], a1 = a[i1];
        a[i0] = f2fma(swp(a1), vs, f2mul(a0, cp));
        a[i1] = f2fma(swp(a0), vs, f2mul(a1, cp));
    }
}

// ---------------- layouts & transposes ----------------
// layout 0 (H): reg = local bits 8-11 :  i = r*256 + t
// layout 1 (L): reg = local bits 0-3  :  i = t*16 + r
// layout 2 (M): reg = local bits 4-7  :  i = (t>>4)*256 + r*16 + (t&15)
template<int L>
__device__ __forceinline__ int lidx(int r, int t) {
    return L == 0 ? ((r << 8) | t)
         : L == 1 ? ((t << 4) | r)
                  : (((t >> 4) << 8) | (r << 4) | (t & 15));
}
__device__ __forceinline__ int swz(int i) { return i ^ ((i >> 4) & 0xF); }

template<int F, int T>
__device__ __forceinline__ void xpose(ull* a, ull* s, int t) {
    __syncthreads();
#pragma unroll
    for (int r = 0; r < 16; r++) s[swz(lidx<F>(r, t))] = a[r];
    __syncthreads();
#pragma unroll
    for (int r = 0; r < 16; r++) a[r] = s[swz(lidx<T>(r, t))];
}

// local -> global maps.  A: chunk = g12-15.  B: chunk = g8-11.  C: chunk = g4-7.
__device__ __forceinline__ int gA(int i, int cid) { return i | (cid << 12); }
__device__ __forceinline__ int gB(int i, int cid) { return (i & 0xFF) | (cid << 8) | ((i >> 8) << 12); }
__device__ __forceinline__ int gC(int i, int cid) { return (i & 0xF)  | (cid << 4) | ((i >> 4) << 8); }

// ---------------- shared gate-constant prep (indexed by WIRE) ----------------
__device__ __forceinline__ void prep_gates(
    int t, int b, int uLayer,
    const float* __restrict__ x,  const float* __restrict__ w0,
    const float* __restrict__ x0, const float* __restrict__ w1,
    const float* __restrict__ x1,
    ull (*sUU)[8], float2 (*sF)[2], ull (*sCC0)[2], ull (*sCC1)[2])
{
    if (t < NQ) {
        const int q = t;                              // wire
        const float* w = (uLayer ? w1 : w0) + q * 3;
        float xq = x[b * NQ + q];
        float sx, cx; sincosf(0.5f * xq, &sx, &cx);
        float phi = w[0], th = w[1], om = w[2];
        float sth, cth; sincosf(0.5f * th, &sth, &cth);
        float sp, cp;   sincosf(0.5f * (phi + om), &sp, &cp);
        float sm, cm;   sincosf(0.5f * (phi - om), &sm, &cm);
        float2 ra = make_float2( cp * cth, -sp * cth);
        float2 rb = make_float2(-cm * sth, -sm * sth);
        float2 rc = make_float2( cm * sth, -sm * sth);
        float2 rd = make_float2( cp * cth,  sp * cth);
        float2 U0 = make_float2(ra.x * cx + rb.y * sx,  ra.y * cx - rb.x * sx);
        float2 U1 = make_float2(ra.y * sx + rb.x * cx, -ra.x * sx + rb.y * cx);
        float2 U2 = make_float2(rc.x * cx + rd.y * sx,  rc.y * cx - rd.x * sx);
        float2 U3 = make_float2(rc.y * sx + rd.x * cx, -rc.x * sx + rd.y * cx);
        sUU[q][0] = bc(U0.x); sUU[q][1] = pk(-U0.y, U0.y);
        sUU[q][2] = bc(U1.x); sUU[q][3] = pk(-U1.y, U1.y);
        sUU[q][4] = bc(U2.x); sUU[q][5] = pk(-U2.y, U2.y);
        sUU[q][6] = bc(U3.x); sUU[q][7] = pk(-U3.y, U3.y);
        if (sF) {                                      // init factors (layer 0, column 0)
            int bit = c_w2b[q];
            sF[bit][0] = U0;                           // entry (0,0)
            sF[bit][1] = U2;                           // entry (1,0)
        }
        float a0s, a0c; sincosf(0.5f * x0[q], &a0s, &a0c);
        sCC0[q][0] = bc(a0c); sCC0[q][1] = pk(a0s, -a0s);
        float a1s, a1c; sincosf(0.5f * x1[q], &a1s, &a1c);
        sCC1[q][0] = bc(a1c); sCC1[q][1] = pk(a1s, -a1s);
    }
    __syncthreads();
}

#define SMEM_DECL \
    __shared__ ull s[CHUNK]; \
    __shared__ ull sUU[NQ][8]; \
    __shared__ ull sCC0[NQ][2]; \
    __shared__ ull sCC1[NQ][2];

// ---------------------------------------------------------------------------
// Pass 1 (map A, store only): analytic post-U0 product init, L0 edges e0..e11.
// Edge eq: ctrl = bit of w_q, tgt = bit of w_{q+1}.
__global__ __launch_bounds__(TPB) void k_pass1(
    const float* __restrict__ x,  const float* __restrict__ w0,
    const float* __restrict__ x0, const float* __restrict__ w1,
    const float* __restrict__ x1)
{
    SMEM_DECL
    __shared__ float2 sF[NQ][2];
    const int t = threadIdx.x, cid = blockIdx.x, b = blockIdx.y;
    prep_gates(t, b, 0, x, w0, x0, w1, x1, sUU, sF, sCC0, sCC1);

    ull a[16];
    ull* gs = g_state + (size_t)b * DIM;

    // ---- product init in L layout: g0-3 = r, g4-11 = t, g12-15 = cid ----
    {
        float2 pref = make_float2(1.0f, 0.0f);
#pragma unroll
        for (int bb = 4; bb < 12; bb++)
            pref = cmul(pref, sF[bb][(t >> (bb - 4)) & 1]);
#pragma unroll
        for (int bb = 12; bb < 16; bb++)
            pref = cmul(pref, sF[bb][(cid >> (bb - 12)) & 1]);
        float2 g01[4], g23[4];
#pragma unroll
        for (int i = 0; i < 4; i++) {
            g01[i] = cmul(sF[0][i & 1], sF[1][(i >> 1) & 1]);
            g23[i] = cmul(sF[2][i & 1], sF[3][(i >> 1) & 1]);
        }
#pragma unroll
        for (int r = 0; r < 16; r++) {
            float2 v = cmul(pref, cmul(g01[r & 3], g23[r >> 2]));
            a[r] = pk(v.x, v.y);
        }
    }
    // L (regs = g0-3): e0 ctrl g15=cid3 -> tgt g0; e1..e3 in-reg
    if ((cid >> 3) & 1) gRX<0>(a, sCC0[0][0], sCC0[0][1]);     // e0
    gCRX<1, 0>(a, sCC0[1][0], sCC0[1][1]);                      // e1: g0->g1
    gCRX<2, 1>(a, sCC0[2][0], sCC0[2][1]);                      // e2
    gCRX<3, 2>(a, sCC0[3][0], sCC0[3][1]);                      // e3
    xpose<1, 2>(a, s, t);
    // M (regs = g4-7; g0-3 = t&15): e4 ctrl g3 = t bit3
    if ((t >> 3) & 1) gRX<0>(a, sCC0[4][0], sCC0[4][1]);        // e4: g3->g4
    gCRX<1, 0>(a, sCC0[5][0], sCC0[5][1]);                      // e5
    gCRX<2, 1>(a, sCC0[6][0], sCC0[6][1]);                      // e6
    gCRX<3, 2>(a, sCC0[7][0], sCC0[7][1]);                      // e7
    xpose<2, 0>(a, s, t);
    // H (regs = g8-11; g0-7 = t): e8 ctrl g7 = t bit7
    if ((t >> 7) & 1) gRX<0>(a, sCC0[8][0], sCC0[8][1]);        // e8: g7->g8
    gCRX<1, 0>(a, sCC0[ 9][0], sCC0[ 9][1]);                    // e9
    gCRX<2, 1>(a, sCC0[10][0], sCC0[10][1]);                    // e10
    gCRX<3, 2>(a, sCC0[11][0], sCC0[11][1]);                    // e11
#pragma unroll
    for (int r = 0; r < 16; r++) gs[gA(lidx<0>(r, t), cid)] = a[r];
}

// Pass 2 (map B): L0 e12..e15, U1 on w13..w15,w0,w1..w8, L1 e0..e7.
// Map B: local 0-7 = g0-7, local 8-11 = g12-15, cid = g8-11.
__global__ __launch_bounds__(TPB) void k_pass2(
    const float* __restrict__ x,  const float* __restrict__ w0,
    const float* __restrict__ x0, const float* __restrict__ w1,
    const float* __restrict__ x1)
{
    SMEM_DECL
    const int t = threadIdx.x, cid = blockIdx.x, b = blockIdx.y;
    prep_gates(t, b, 1, x, w0, x0, w1, x1, sUU, nullptr, sCC0, sCC1);

    ull a[16];
    ull* gs = g_state + (size_t)b * DIM;
    // load H (regs = l8-11 = g12-15; t = l0-7 = g0-7)
#pragma unroll
    for (int r = 0; r < 16; r++) a[r] = gs[gB(lidx<0>(r, t), cid)];
    // L0 e12: ctrl g11 = cid bit3 -> tgt g12 (reg0)
    if ((cid >> 3) & 1) gRX<0>(a, sCC0[12][0], sCC0[12][1]);    // e12
    gCRX<1, 0>(a, sCC0[13][0], sCC0[13][1]);                    // e13: g12->g13
    gCRX<2, 1>(a, sCC0[14][0], sCC0[14][1]);                    // e14
    gCRX<3, 2>(a, sCC0[15][0], sCC0[15][1]);                    // e15: g14->g15  (L0 done)
    // U1 on w13(g12),w14(g13),w15(g14),w0(g15)
    gU<0>(a, sUU[13]); gU<1>(a, sUU[14]); gU<2>(a, sUU[15]); gU<3>(a, sUU[0]);
    xpose<0, 1>(a, s, t);
    // L (regs = g0-3; t bits 0-3 = g4-7, t bits 4-7 = g12-15)
    gU<0>(a, sUU[1]); gU<1>(a, sUU[2]); gU<2>(a, sUU[3]); gU<3>(a, sUU[4]);
    // L1 e0: ctrl g15 = t bit7 -> tgt g0
    if ((t >> 7) & 1) gRX<0>(a, sCC1[0][0], sCC1[0][1]);        // e0 (L1)
    gCRX<1, 0>(a, sCC1[1][0], sCC1[1][1]);                      // e1
    gCRX<2, 1>(a, sCC1[2][0], sCC1[2][1]);                      // e2
    gCRX<3, 2>(a, sCC1[3][0], sCC1[3][1]);                      // e3
    xpose<1, 2>(a, s, t);
    // M (regs = g4-7; t bits 0-3 = g0-3)
    gU<0>(a, sUU[5]); gU<1>(a, sUU[6]); gU<2>(a, sUU[7]); gU<3>(a, sUU[8]);
    // L1 e4: ctrl g3 = t bit3 -> tgt g4
    if ((t >> 3) & 1) gRX<0>(a, sCC1[4][0], sCC1[4][1]);        // e4 (L1)
    gCRX<1, 0>(a, sCC1[5][0], sCC1[5][1]);                      // e5
    gCRX<2, 1>(a, sCC1[6][0], sCC1[6][1]);                      // e6
    gCRX<3, 2>(a, sCC1[7][0], sCC1[7][1]);                      // e7
#pragma unroll
    for (int r = 0; r < 16; r++) gs[gB(lidx<2>(r, t), cid)] = a[r];
}

// Pass 3 (map C, load only): U1 on w9..w12, L1 e8..e15, measurement.
// Map C: local 0-3 = g0-3, local 4-11 = g8-15, cid = g4-7.
__global__ __launch_bounds__(TPB) void k_pass3(
    const float* __restrict__ x,  const float* __restrict__ w0,
    const float* __restrict__ x0, const float* __restrict__ w1,
    const float* __restrict__ x1)
{
    SMEM_DECL
    __shared__ float sred[8][NQ];
    const int t = threadIdx.x, cid = blockIdx.x, b = blockIdx.y;
    prep_gates(t, b, 1, x, w0, x0, w1, x1, sUU, nullptr, sCC0, sCC1);

    ull a[16];
    ull* gs = g_state + (size_t)b * DIM;
    // load M (regs = l4-7 = g8-11; t bits 0-3 = g0-3, t bits 4-7 = g12-15)
#pragma unroll
    for (int r = 0; r < 16; r++) a[r] = gs[gC(lidx<2>(r, t), cid)];
    // U1 on w9(g8),w10(g9),w11(g10),w12(g11)
    gU<0>(a, sUU[9]); gU<1>(a, sUU[10]); gU<2>(a, sUU[11]); gU<3>(a, sUU[12]);
    // L1 e8: ctrl g7 = cid bit3 -> tgt g8 (reg0)
    if ((cid >> 3) & 1) gRX<0>(a, sCC1[8][0], sCC1[8][1]);      // e8 (L1)
    gCRX<1, 0>(a, sCC1[ 9][0], sCC1[ 9][1]);                    // e9
    gCRX<2, 1>(a, sCC1[10][0], sCC1[10][1]);                    // e10
    gCRX<3, 2>(a, sCC1[11][0], sCC1[11][1]);                    // e11
    xpose<2, 0>(a, s, t);
    // H (regs = l8-11 = g12-15; t bits 0-3 = g0-3, t bits 4-7 = g8-11)
    // L1 e12: ctrl g11 = t bit7 -> tgt g12
    if ((t >> 7) & 1) gRX<0>(a, sCC1[12][0], sCC1[12][1]);      // e12 (L1)
    gCRX<1, 0>(a, sCC1[13][0], sCC1[13][1]);                    // e13
    gCRX<2, 1>(a, sCC1[14][0], sCC1[14][1]);                    // e14
    gCRX<3, 2>(a, sCC1[15][0], sCC1[15][1]);                    // e15 (L1 done)

    // ---- measurement (H layout, map C): g0-3 = t&15, g4-7 = cid, g8-11 = t>>4, g12-15 = r
    float p[16], S = 0.0f;
#pragma unroll
    for (int r = 0; r < 16; r++) {
        float xx, yy; upk(a[r], xx, yy);
        p[r] = xx * xx + yy * yy;
        S += p[r];
    }
    float acc[NQ];
#pragma unroll
    for (int bit = 0; bit < 4; bit++)   acc[bit] = ((t >> bit) & 1) ? -S : S;
#pragma unroll
    for (int bit = 4; bit < 8; bit++)   acc[bit] = ((cid >> (bit - 4)) & 1) ? -S : S;
#pragma unroll
    for (int bit = 8; bit < 12; bit++)  acc[bit] = ((t >> (bit - 4)) & 1) ? -S : S;
#pragma unroll
    for (int bit = 12; bit < 16; bit++) {
        float v = 0.0f;
#pragma unroll
        for (int r = 0; r < 16; r++) v += ((r >> (bit - 12)) & 1) ? -p[r] : p[r];
        acc[bit] = v;
    }
#pragma unroll
    for (int i = 0; i < NQ; i++) {
#pragma unroll
        for (int o = 16; o >= 1; o >>= 1)
            acc[i] += __shfl_down_sync(0xFFFFFFFFu, acc[i], o);
    }
    __syncthreads();
    int warp = t >> 5, lane = t & 31;
    if (lane == 0) {
#pragma unroll
        for (int i = 0; i < NQ; i++) sred[warp][i] = acc[i];
    }
    __syncthreads();
    if (t < NQ) {
        float sum = 0.0f;
#pragma unroll
        for (int wI = 0; wI < 8; wI++) sum += sred[wI][t];
        g_part[b][cid][t] = sum;      // indexed by BIT
    }
}

// ---------------------------------------------------------------------------
__global__ void k_final(const float* __restrict__ fc_w,
                        const float* __restrict__ fc_b,
                        float* __restrict__ out) {
    int b = blockIdx.x;
    int t = threadIdx.x;
    __shared__ float feats[NQ];
    __shared__ float logits[NCLS];
    if (t < NQ) {
        float sum = 0.0f;
        int bit = c_w2b[t];               // wire t measures its assigned bit
#pragma unroll
        for (int c = 0; c < NCHUNK; c++) sum += g_part[b][c][bit];
        feats[t] = sum;
    }
    __syncthreads();
    if (t < NCLS) {
        float z = fc_b[t];
#pragma unroll
        for (int wI = 0; wI < NQ; wI++) z += feats[wI] * fc_w[t * NQ + wI];
        logits[t] = z;
    }
    __syncthreads();
    if (t == 0) {
        float mx = logits[0];
        for (int c = 1; c < NCLS; c++) mx = fmaxf(mx, logits[c]);
        float sum = 0.0f;
        for (int c = 0; c < NCLS; c++) sum += expf(logits[c] - mx);
        float l = logf(sum) + mx;
        for (int c = 0; c < NCLS; c++) out[b * NCLS + c] = logits[c] - l;
    }
}

// ---------------------------------------------------------------------------
extern "C" void kernel_launch(void* const* d_in, const int* in_sizes, int n_in,
                              void* d_out, int out_size) {
    const float* x    = (const float*)d_in[0];
    const float* w0   = (const float*)d_in[1];
    const float* x0   = (const float*)d_in[2];
    const float* w1   = (const float*)d_in[3];
    const float* x1   = (const float*)d_in[4];
    const float* fc_w = (const float*)d_in[5];
    const float* fc_b = (const float*)d_in[6];
    float* out = (float*)d_out;

    dim3 grid(NCHUNK, BATCH);
    k_pass1<<<grid, TPB>>>(x, w0, x0, w1, x1);
    k_pass2<<<grid, TPB>>>(x, w0, x0, w1, x1);
    k_pass3<<<grid, TPB>>>(x, w0, x0, w1, x1);
    k_final<<<BATCH, 32>>>(fc_w, fc_b, out);
}